// round 1
// baseline (speedup 1.0000x reference)
#include <cuda_runtime.h>

#define NNODES 50000
#define DEG 16
#define FDIM 128

// Scratch (device globals: allocation-free, per the harness rules)
__device__ __align__(16) float g_A[NNODES * FDIM];
__device__ __align__(16) float g_B[NNODES * FDIM];
__device__ __align__(16) float g_xnew[NNODES * FDIM];
__device__ __align__(16) float g_support[NNODES * FDIM];

// ---------------------------------------------------------------------------
// C[nrows,128] = X[nrows,128] @ W[128,128]   (W row-major)
// Block tile: 64 rows x 128 cols, 256 threads, per-thread 4x8 register tile.
// Xs stored k-major (transposed) so the 4-row operand is one LDS.128.
// ---------------------------------------------------------------------------
__global__ __launch_bounds__(256, 2) void gemm128_kernel(
    const float* __restrict__ X, const float* __restrict__ W,
    float* __restrict__ C, int nrows)
{
    __shared__ float Xs[16][64];    // [k][row]
    __shared__ float Ws[16][128];   // [k][col]

    const int tid = threadIdx.x;
    const int tr  = tid >> 4;   // 0..15 -> rows tr*4 .. tr*4+3
    const int tc  = tid & 15;   // 0..15 -> cols tc*8 .. tc*8+7
    const int rowBase = blockIdx.x * 64;

    float acc[4][8];
#pragma unroll
    for (int i = 0; i < 4; ++i)
#pragma unroll
        for (int j = 0; j < 8; ++j) acc[i][j] = 0.f;

    const int lr = tid >> 2;         // 0..63  (row within tile for X load)
    const int lk = (tid & 3) << 2;   // 0,4,8,12 (k offset for X load)

    for (int k0 = 0; k0 < 128; k0 += 16) {
        // Load X tile (coalesced float4 from gmem, transposed scatter to smem)
        {
            float4 v = make_float4(0.f, 0.f, 0.f, 0.f);
            int grow = rowBase + lr;
            if (grow < nrows)
                v = *(const float4*)(X + (size_t)grow * FDIM + k0 + lk);
            Xs[lk + 0][lr] = v.x;
            Xs[lk + 1][lr] = v.y;
            Xs[lk + 2][lr] = v.z;
            Xs[lk + 3][lr] = v.w;
        }
        // Load W tile: 16 x 128 = 512 float4, 2 per thread
#pragma unroll
        for (int it = 0; it < 2; ++it) {
            int idx = tid + it * 256;       // 0..511
            int kr  = idx >> 5;             // 0..15
            int c4  = (idx & 31) << 2;      // 0..124
            *(float4*)(&Ws[kr][c4]) =
                *(const float4*)(W + (size_t)(k0 + kr) * FDIM + c4);
        }
        __syncthreads();

#pragma unroll
        for (int kk = 0; kk < 16; ++kk) {
            float4 a4 = *(const float4*)(&Xs[kk][tr << 2]);
            float4 b0 = *(const float4*)(&Ws[kk][tc << 3]);
            float4 b1 = *(const float4*)(&Ws[kk][(tc << 3) + 4]);
            float av[4] = {a4.x, a4.y, a4.z, a4.w};
            float bv[8] = {b0.x, b0.y, b0.z, b0.w, b1.x, b1.y, b1.z, b1.w};
#pragma unroll
            for (int i = 0; i < 4; ++i)
#pragma unroll
                for (int j = 0; j < 8; ++j)
                    acc[i][j] = fmaf(av[i], bv[j], acc[i][j]);
        }
        __syncthreads();
    }

#pragma unroll
    for (int i = 0; i < 4; ++i) {
        int grow = rowBase + (tr << 2) + i;
        if (grow < nrows) {
            *(float4*)(C + (size_t)grow * FDIM + (tc << 3)) =
                make_float4(acc[i][0], acc[i][1], acc[i][2], acc[i][3]);
            *(float4*)(C + (size_t)grow * FDIM + (tc << 3) + 4) =
                make_float4(acc[i][4], acc[i][5], acc[i][6], acc[i][7]);
        }
    }
}

__device__ __forceinline__ float sigf(float z)
{
    return __fdividef(1.f, 1.f + __expf(-z));
}

// ---------------------------------------------------------------------------
// x_new[i] = x[i] + sum_e sigmoid(A[i] + B[src_e]) * x[src_e]
// warp per node, lane handles 4 features (float4). Edges of node i are
// contiguous at [i*16, i*16+16) because edge_dst = repeat(arange(N), 16).
// ---------------------------------------------------------------------------
__global__ __launch_bounds__(256) void edge_mask_kernel(
    const float* __restrict__ x, const int* __restrict__ edge_src)
{
    int node = blockIdx.x * 8 + (threadIdx.x >> 5);
    if (node >= NNODES) return;
    int lane = threadIdx.x & 31;

    const float4* x4 = (const float4*)x;
    const float4* A4 = (const float4*)g_A;
    const float4* B4 = (const float4*)g_B;

    float4 a = A4[node * 32 + lane];
    float4 acc = make_float4(0.f, 0.f, 0.f, 0.f);
    int ebase = node * DEG;
#pragma unroll
    for (int e = 0; e < DEG; ++e) {
        int src = __ldg(edge_src + ebase + e);
        float4 b  = B4[src * 32 + lane];
        float4 xv = x4[src * 32 + lane];
        acc.x = fmaf(sigf(a.x + b.x), xv.x, acc.x);
        acc.y = fmaf(sigf(a.y + b.y), xv.y, acc.y);
        acc.z = fmaf(sigf(a.z + b.z), xv.z, acc.z);
        acc.w = fmaf(sigf(a.w + b.w), xv.w, acc.w);
    }
    float4 xs = x4[node * 32 + lane];
    ((float4*)g_xnew)[node * 32 + lane] =
        make_float4(xs.x + acc.x, xs.y + acc.y, xs.z + acc.z, xs.w + acc.w);
}

// ---------------------------------------------------------------------------
// out[i] = bias + sum_e adj[e] * support[src_e]
// ---------------------------------------------------------------------------
__global__ __launch_bounds__(256) void out_kernel(
    const float* __restrict__ adj_vals, const int* __restrict__ edge_src,
    const float* __restrict__ bias, float* __restrict__ out)
{
    int node = blockIdx.x * 8 + (threadIdx.x >> 5);
    if (node >= NNODES) return;
    int lane = threadIdx.x & 31;

    const float4* S4 = (const float4*)g_support;
    float4 acc = ((const float4*)bias)[lane];
    int ebase = node * DEG;
#pragma unroll
    for (int e = 0; e < DEG; ++e) {
        int src  = __ldg(edge_src + ebase + e);
        float av = __ldg(adj_vals + ebase + e);
        float4 s = S4[src * 32 + lane];
        acc.x = fmaf(av, s.x, acc.x);
        acc.y = fmaf(av, s.y, acc.y);
        acc.z = fmaf(av, s.z, acc.z);
        acc.w = fmaf(av, s.w, acc.w);
    }
    ((float4*)out)[node * 32 + lane] = acc;
}

extern "C" void kernel_launch(void* const* d_in, const int* in_sizes, int n_in,
                              void* d_out, int out_size)
{
    const float* x      = (const float*)d_in[0];
    const float* weight = (const float*)d_in[1];
    const float* bias   = (const float*)d_in[2];
    const float* wmask  = (const float*)d_in[3];  // [256,128] row-major
    const float* adj    = (const float*)d_in[4];
    const int*   esrc   = (const int*)d_in[5];
    // d_in[6] = edge_dst: implicit (repeat(arange(N), 16)), not needed
    float* out = (float*)d_out;

    float *A, *B, *xnew, *support;
    cudaGetSymbolAddress((void**)&A, g_A);
    cudaGetSymbolAddress((void**)&B, g_B);
    cudaGetSymbolAddress((void**)&xnew, g_xnew);
    cudaGetSymbolAddress((void**)&support, g_support);

    const int ggrid = (NNODES + 63) / 64;          // 782
    const int egrid = (NNODES + 7) / 8;            // 6250

    // A = x @ Wm[0:128,:]   (rows of Wm that multiply the center features)
    gemm128_kernel<<<ggrid, 256>>>(x, wmask, A, NNODES);
    // B = x @ Wm[128:256,:] (rows that multiply the neighbor features)
    gemm128_kernel<<<ggrid, 256>>>(x, wmask + 128 * 128, B, NNODES);
    // x_new = x + segment_sum(sigmoid(A[dst]+B[src]) * x[src])
    edge_mask_kernel<<<egrid, 256>>>(x, esrc);
    // support = x_new @ weight
    gemm128_kernel<<<ggrid, 256>>>(xnew, weight, support, NNODES);
    // out = segment_sum(adj * support[src]) + bias
    out_kernel<<<egrid, 256>>>(adj, esrc, bias, out);
}

// round 4
// speedup vs baseline: 2.3512x; 2.3512x over previous
#include <cuda_runtime.h>
#include <cstdint>

#define NNODES 50000
#define DEG 16
#define FDIM 128

// Scratch (device globals: allocation-free per harness rules)
__device__ __align__(16) float g_A[NNODES * FDIM];
__device__ __align__(16) float g_B[NNODES * FDIM];
__device__ __align__(16) float g_xnew[NNODES * FDIM];
__device__ __align__(16) float g_support[NNODES * FDIM];

// ---------------------------------------------------------------------------
// tf32 helpers (3xTF32 decomposition: x = hi + lo, both tf32-representable)
// ---------------------------------------------------------------------------
__device__ __forceinline__ float tf32_rna(float x)
{
    uint32_t r;
    asm("cvt.rna.tf32.f32 %0, %1;" : "=r"(r) : "f"(x));
    return __uint_as_float(r);
}

__device__ __forceinline__ void split4(float4 v, float4& hi, float4& lo)
{
    hi.x = tf32_rna(v.x); lo.x = tf32_rna(v.x - hi.x);
    hi.y = tf32_rna(v.y); lo.y = tf32_rna(v.y - hi.y);
    hi.z = tf32_rna(v.z); lo.z = tf32_rna(v.z - hi.z);
    hi.w = tf32_rna(v.w); lo.w = tf32_rna(v.w - hi.w);
}

__device__ __forceinline__ void mma_tf32(float c[4], const uint32_t a[4],
                                         const uint32_t b[2])
{
    asm volatile(
        "mma.sync.aligned.m16n8k8.row.col.f32.tf32.tf32.f32 "
        "{%0,%1,%2,%3}, {%4,%5,%6,%7}, {%8,%9}, {%0,%1,%2,%3};\n"
        : "+f"(c[0]), "+f"(c[1]), "+f"(c[2]), "+f"(c[3])
        : "r"(a[0]), "r"(a[1]), "r"(a[2]), "r"(a[3]), "r"(b[0]), "r"(b[1]));
}

// ---------------------------------------------------------------------------
// C[nrows,128] = X[nrows,128] @ W[128,128] via 3xTF32 tensor-core MMA.
// Block: 256 threads, tile M=128 x N=128, K staged 16 at a time.
// Warp tile m32 x n64 (2 x 8 m16n8k8 fragments), 3 mma per fragment pair.
// Smem strides (20, 136) make every fragment LDS.32 bank-conflict-free.
// ---------------------------------------------------------------------------
__global__ __launch_bounds__(256, 2) void gemm_tf32(
    const float* __restrict__ X, const float* __restrict__ W,
    float* __restrict__ C, int nrows)
{
    __shared__ float Xhi[128][20];
    __shared__ float Xlo[128][20];
    __shared__ float Whi[16][136];
    __shared__ float Wlo[16][136];

    const int tid  = threadIdx.x;
    const int lane = tid & 31;
    const int warp = tid >> 5;
    const int g    = lane >> 2;     // group id (0..7)
    const int tq   = lane & 3;      // thread-in-group (0..3)
    const int wm   = warp & 3;      // M quadrant -> rows wm*32
    const int wn   = warp >> 2;     // N half    -> cols wn*64
    const int rowBase = blockIdx.x * 128;

    float acc[2][8][4];
#pragma unroll
    for (int mt = 0; mt < 2; ++mt)
#pragma unroll
        for (int nt = 0; nt < 8; ++nt)
#pragma unroll
            for (int i = 0; i < 4; ++i) acc[mt][nt][i] = 0.f;

    for (int k0 = 0; k0 < 128; k0 += 16) {
        // Stage X tile [128 rows x 16 k] as hi/lo (2 float4 per thread)
#pragma unroll
        for (int it = 0; it < 2; ++it) {
            int idx = tid + it * 256;          // 0..511
            int r   = idx >> 2;                // 0..127
            int kq  = (idx & 3) << 2;          // 0,4,8,12
            float4 v = make_float4(0.f, 0.f, 0.f, 0.f);
            int gr = rowBase + r;
            if (gr < nrows)
                v = *(const float4*)(X + (size_t)gr * FDIM + k0 + kq);
            float4 h, l;
            split4(v, h, l);
            *(float4*)&Xhi[r][kq] = h;
            *(float4*)&Xlo[r][kq] = l;
        }
        // Stage W tile [16 k x 128 n] as hi/lo (2 float4 per thread)
#pragma unroll
        for (int it = 0; it < 2; ++it) {
            int idx = tid + it * 256;          // 0..511
            int kr  = idx >> 5;                // 0..15
            int n4  = (idx & 31) << 2;         // 0..124
            float4 v = *(const float4*)(W + (size_t)(k0 + kr) * FDIM + n4);
            float4 h, l;
            split4(v, h, l);
            *(float4*)&Whi[kr][n4] = h;
            *(float4*)&Wlo[kr][n4] = l;
        }
        __syncthreads();

#pragma unroll
        for (int kb = 0; kb < 16; kb += 8) {
            uint32_t ahi[2][4], alo[2][4];
#pragma unroll
            for (int mt = 0; mt < 2; ++mt) {
                int r0 = wm * 32 + mt * 16 + g;
                ahi[mt][0] = __float_as_uint(Xhi[r0    ][kb + tq    ]);
                ahi[mt][1] = __float_as_uint(Xhi[r0 + 8][kb + tq    ]);
                ahi[mt][2] = __float_as_uint(Xhi[r0    ][kb + tq + 4]);
                ahi[mt][3] = __float_as_uint(Xhi[r0 + 8][kb + tq + 4]);
                alo[mt][0] = __float_as_uint(Xlo[r0    ][kb + tq    ]);
                alo[mt][1] = __float_as_uint(Xlo[r0 + 8][kb + tq    ]);
                alo[mt][2] = __float_as_uint(Xlo[r0    ][kb + tq + 4]);
                alo[mt][3] = __float_as_uint(Xlo[r0 + 8][kb + tq + 4]);
            }
#pragma unroll
            for (int nt = 0; nt < 8; ++nt) {
                int n = wn * 64 + nt * 8 + g;
                uint32_t bhi[2], blo[2];
                bhi[0] = __float_as_uint(Whi[kb + tq    ][n]);
                bhi[1] = __float_as_uint(Whi[kb + tq + 4][n]);
                blo[0] = __float_as_uint(Wlo[kb + tq    ][n]);
                blo[1] = __float_as_uint(Wlo[kb + tq + 4][n]);
#pragma unroll
                for (int mt = 0; mt < 2; ++mt) {
                    mma_tf32(acc[mt][nt], ahi[mt], bhi);   // hi*hi
                    mma_tf32(acc[mt][nt], ahi[mt], blo);   // hi*lo
                    mma_tf32(acc[mt][nt], alo[mt], bhi);   // lo*hi
                }
            }
        }
        __syncthreads();
    }

    // Epilogue: c0,c1 -> (row, 2tq..2tq+1), c2,c3 -> (row+8, same cols)
#pragma unroll
    for (int mt = 0; mt < 2; ++mt) {
        int r0 = rowBase + wm * 32 + mt * 16 + g;
#pragma unroll
        for (int nt = 0; nt < 8; ++nt) {
            int n = wn * 64 + nt * 8 + 2 * tq;
            if (r0 < nrows)
                *(float2*)(C + (size_t)r0 * FDIM + n) =
                    make_float2(acc[mt][nt][0], acc[mt][nt][1]);
            if (r0 + 8 < nrows)
                *(float2*)(C + (size_t)(r0 + 8) * FDIM + n) =
                    make_float2(acc[mt][nt][2], acc[mt][nt][3]);
        }
    }
}

__device__ __forceinline__ float sigf(float z)
{
    return __fdividef(1.f, 1.f + __expf(-z));
}

// ---------------------------------------------------------------------------
// x_new[i] = x[i] + sum_e sigmoid(A[i] + B[src_e]) * x[src_e]
// ---------------------------------------------------------------------------
__global__ __launch_bounds__(256) void edge_mask_kernel(
    const float* __restrict__ x, const int* __restrict__ edge_src)
{
    int node = blockIdx.x * 8 + (threadIdx.x >> 5);
    if (node >= NNODES) return;
    int lane = threadIdx.x & 31;

    const float4* x4 = (const float4*)x;
    const float4* A4 = (const float4*)g_A;
    const float4* B4 = (const float4*)g_B;

    float4 a = A4[node * 32 + lane];
    float4 acc = make_float4(0.f, 0.f, 0.f, 0.f);
    int ebase = node * DEG;
#pragma unroll
    for (int e = 0; e < DEG; ++e) {
        int src = __ldg(edge_src + ebase + e);
        float4 b  = B4[src * 32 + lane];
        float4 xv = x4[src * 32 + lane];
        acc.x = fmaf(sigf(a.x + b.x), xv.x, acc.x);
        acc.y = fmaf(sigf(a.y + b.y), xv.y, acc.y);
        acc.z = fmaf(sigf(a.z + b.z), xv.z, acc.z);
        acc.w = fmaf(sigf(a.w + b.w), xv.w, acc.w);
    }
    float4 xs = x4[node * 32 + lane];
    ((float4*)g_xnew)[node * 32 + lane] =
        make_float4(xs.x + acc.x, xs.y + acc.y, xs.z + acc.z, xs.w + acc.w);
}

// ---------------------------------------------------------------------------
// out[i] = bias + sum_e adj[e] * support[src_e]
// ---------------------------------------------------------------------------
__global__ __launch_bounds__(256) void out_kernel(
    const float* __restrict__ adj_vals, const int* __restrict__ edge_src,
    const float* __restrict__ bias, float* __restrict__ out)
{
    int node = blockIdx.x * 8 + (threadIdx.x >> 5);
    if (node >= NNODES) return;
    int lane = threadIdx.x & 31;

    const float4* S4 = (const float4*)g_support;
    float4 acc = ((const float4*)bias)[lane];
    int ebase = node * DEG;
#pragma unroll
    for (int e = 0; e < DEG; ++e) {
        int src  = __ldg(edge_src + ebase + e);
        float av = __ldg(adj_vals + ebase + e);
        float4 s = S4[src * 32 + lane];
        acc.x = fmaf(av, s.x, acc.x);
        acc.y = fmaf(av, s.y, acc.y);
        acc.z = fmaf(av, s.z, acc.z);
        acc.w = fmaf(av, s.w, acc.w);
    }
    ((float4*)out)[node * 32 + lane] = acc;
}

extern "C" void kernel_launch(void* const* d_in, const int* in_sizes, int n_in,
                              void* d_out, int out_size)
{
    const float* x      = (const float*)d_in[0];
    const float* weight = (const float*)d_in[1];
    const float* bias   = (const float*)d_in[2];
    const float* wmask  = (const float*)d_in[3];  // [256,128] row-major
    const float* adj    = (const float*)d_in[4];
    const int*   esrc   = (const int*)d_in[5];
    float* out = (float*)d_out;

    float *A, *B, *xnew, *support;
    cudaGetSymbolAddress((void**)&A, g_A);
    cudaGetSymbolAddress((void**)&B, g_B);
    cudaGetSymbolAddress((void**)&xnew, g_xnew);
    cudaGetSymbolAddress((void**)&support, g_support);

    const int ggrid = (NNODES + 127) / 128;        // 391
    const int egrid = (NNODES + 7) / 8;            // 6250

    // A = x @ Wm[0:128,:]  (center half), B = x @ Wm[128:256,:] (neighbor half)
    gemm_tf32<<<ggrid, 256>>>(x, wmask, A, NNODES);
    gemm_tf32<<<ggrid, 256>>>(x, wmask + 128 * 128, B, NNODES);
    // x_new = x + segment_sum(sigmoid(A[dst]+B[src]) * x[src])
    edge_mask_kernel<<<egrid, 256>>>(x, esrc);
    // support = x_new @ weight
    gemm_tf32<<<ggrid, 256>>>(xnew, weight, support, NNODES);
    // out = segment_sum(adj * support[src]) + bias
    out_kernel<<<egrid, 256>>>(adj, esrc, bias, out);
}